// round 3
// baseline (speedup 1.0000x reference)
#include <cuda_runtime.h>
#include <cuda_fp16.h>
#include <cstdint>
#include <cstddef>

#define N_CAP 50000
#define E_CAP 1600000
#define NCOL  640
#define HCOL  320

// Scratch (static __device__ — no allocation in kernel_launch)
__device__ float  gU[128 * NCOL];
__device__ float  gC[NCOL];
__device__ float  gYdst[(size_t)N_CAP * HCOL];   // [A0..A3 | Xv]  fp32
__device__ __half gYB[(size_t)N_CAP * 256];      // [B0..B3]       fp16
__device__ float  gYXn[(size_t)N_CAP * 64];      // [Xn]           fp32
__device__ int    gCount[N_CAP];
__device__ int    gOff[N_CAP + 1];
__device__ int    gCur[N_CAP];
__device__ int    gCsr[E_CAP];

// ---------------------------------------------------------------------------
__global__ void zero_kernel(int N) {
    int i = blockIdx.x * blockDim.x + threadIdx.x;
    if (i < N) gCount[i] = 0;
}

// ---------------------------------------------------------------------------
// Fold weights into U'[128 x 640], c[640]
// col layout: [A heads: 0-255 | Xv: 256-319 | B heads: 320-575 | Xn: 576-639]
//   A_i = Wt_i @ Wa_i[0:64,:]    bias: ba_i + bt_i@(Wa_top + Wa_bot)
//   B_i = Wt_i @ Wa_i[64:128,:]  bias 0
// ---------------------------------------------------------------------------
__global__ void prep_kernel(const float* __restrict__ Wv, const float* __restrict__ bv,
                            const float* __restrict__ Wn, const float* __restrict__ bn,
                            const float* __restrict__ Wt, const float* __restrict__ bt,
                            const float* __restrict__ Wa, const float* __restrict__ ba) {
    int tid = blockIdx.x * blockDim.x + threadIdx.x;
    if (tid < 128 * NCOL) {
        int k = tid / NCOL;
        int col = tid % NCOL;
        float v;
        if (col < 256 || (col >= 320 && col < 576)) {
            int top = (col < 256) ? 1 : 0;
            int cc = top ? col : (col - 320);
            int i = (cc >> 6) & 3;
            int j = cc & 63;
            const float* wt = Wt + ((size_t)i * 128 + k) * 64;        // Wt[i][k][*]
            const float* wa = Wa + (size_t)i * 128 * 64 + (top ? 0 : 64 * 64) + j;
            float s = 0.f;
            #pragma unroll 8
            for (int m = 0; m < 64; m++) s += wt[m] * wa[m * 64];
            v = s;
        } else if (col < 320) {
            v = Wv[k * 64 + (col - 256)];
        } else {
            v = Wn[k * 64 + (col - 576)];
        }
        gU[tid] = v;
    }
    if (tid < NCOL) {
        float c;
        if (tid < 256) {
            int i = tid >> 6, j = tid & 63;
            const float* btp = bt + i * 64;
            const float* wa = Wa + (size_t)i * 128 * 64 + j;
            float s = ba[i * 64 + j];
            #pragma unroll 8
            for (int m = 0; m < 64; m++)
                s += btp[m] * (wa[m * 64] + wa[(64 + m) * 64]);
            c = s;
        } else if (tid < 320) {
            c = bv[tid - 256];
        } else if (tid < 576) {
            c = 0.f;
        } else {
            c = bn[tid - 576];
        }
        gC[tid] = c;
    }
}

// ---------------------------------------------------------------------------
// TF32 tensor-core GEMM: Y[M x 640] = X[M x 128] @ U'[128 x 640] + c
// BM=128, BN=64, full K=128 resident in smem. 8 warps, 32x32 per warp.
// Epilogue routes: cols<320 -> gYdst (fp32); 320..575 -> gYB (fp16);
//                  576..639 -> gYXn (fp32).
// ---------------------------------------------------------------------------
#define A_LD 132
#define B_LD 72
#define GEMM_SMEM ((128 * A_LD + 128 * B_LD) * 4)

__device__ __forceinline__ uint32_t f2tf32(float f) {
    uint32_t r;
    asm("cvt.rna.tf32.f32 %0, %1;" : "=r"(r) : "f"(f));
    return r;
}

__global__ __launch_bounds__(256) void gemm_tc_kernel(const float* __restrict__ X, int M) {
    extern __shared__ float smem[];
    float* As = smem;                 // [128][132]
    float* Bs = smem + 128 * A_LD;    // [128][72]

    int tid = threadIdx.x;
    int bm = blockIdx.x * 128;
    int bnblk = blockIdx.y * 64;

    #pragma unroll
    for (int it = 0; it < 16; it++) {
        int idx = tid + it * 256;
        int r = idx >> 5;
        int c4 = (idx & 31) << 2;
        float4 v = make_float4(0.f, 0.f, 0.f, 0.f);
        if (bm + r < M) v = *(const float4*)(X + (size_t)(bm + r) * 128 + c4);
        float4 o;
        o.x = __uint_as_float(f2tf32(v.x));
        o.y = __uint_as_float(f2tf32(v.y));
        o.z = __uint_as_float(f2tf32(v.z));
        o.w = __uint_as_float(f2tf32(v.w));
        *(float4*)(As + r * A_LD + c4) = o;
    }
    #pragma unroll
    for (int it = 0; it < 8; it++) {
        int idx = tid + it * 256;
        int k = idx >> 4;
        int c4 = (idx & 15) << 2;
        float4 v = *(const float4*)(gU + (size_t)k * NCOL + bnblk + c4);
        float4 o;
        o.x = __uint_as_float(f2tf32(v.x));
        o.y = __uint_as_float(f2tf32(v.y));
        o.z = __uint_as_float(f2tf32(v.z));
        o.w = __uint_as_float(f2tf32(v.w));
        *(float4*)(Bs + k * B_LD + c4) = o;
    }
    __syncthreads();

    int w = tid >> 5, lane = tid & 31;
    int g = lane >> 2, tig = lane & 3;
    int wm = (w >> 1) * 32;
    int wn = (w & 1) * 32;

    float acc[2][4][4];
    #pragma unroll
    for (int mt = 0; mt < 2; mt++)
        #pragma unroll
        for (int nt = 0; nt < 4; nt++)
            #pragma unroll
            for (int q = 0; q < 4; q++) acc[mt][nt][q] = 0.f;

    #pragma unroll
    for (int kc = 0; kc < 16; kc++) {
        int kb = kc * 8;
        uint32_t a[2][4], b[4][2];
        #pragma unroll
        for (int mt = 0; mt < 2; mt++) {
            int r0 = wm + mt * 16 + g;
            a[mt][0] = __float_as_uint(As[r0 * A_LD + kb + tig]);
            a[mt][1] = __float_as_uint(As[(r0 + 8) * A_LD + kb + tig]);
            a[mt][2] = __float_as_uint(As[r0 * A_LD + kb + tig + 4]);
            a[mt][3] = __float_as_uint(As[(r0 + 8) * A_LD + kb + tig + 4]);
        }
        #pragma unroll
        for (int nt = 0; nt < 4; nt++) {
            int n0 = wn + nt * 8 + g;
            b[nt][0] = __float_as_uint(Bs[(kb + tig) * B_LD + n0]);
            b[nt][1] = __float_as_uint(Bs[(kb + tig + 4) * B_LD + n0]);
        }
        #pragma unroll
        for (int mt = 0; mt < 2; mt++)
            #pragma unroll
            for (int nt = 0; nt < 4; nt++) {
                asm volatile(
                    "mma.sync.aligned.m16n8k8.row.col.f32.tf32.tf32.f32 "
                    "{%0,%1,%2,%3}, {%4,%5,%6,%7}, {%8,%9}, {%0,%1,%2,%3};\n"
                    : "+f"(acc[mt][nt][0]), "+f"(acc[mt][nt][1]),
                      "+f"(acc[mt][nt][2]), "+f"(acc[mt][nt][3])
                    : "r"(a[mt][0]), "r"(a[mt][1]), "r"(a[mt][2]), "r"(a[mt][3]),
                      "r"(b[nt][0]), "r"(b[nt][1]));
            }
    }

    // --- Epilogue: add bias, route by column block ---
    #pragma unroll
    for (int nt = 0; nt < 4; nt++) {
        int cg = wn + nt * 8 + tig * 2;
        float bx = gC[bnblk + cg];
        float by = gC[bnblk + cg + 1];
        #pragma unroll
        for (int mt = 0; mt < 2; mt++) {
            #pragma unroll
            for (int half_ : {0, 1}) {
                int r = bm + wm + mt * 16 + g + half_ * 8;
                if (r < M) {
                    float vx = acc[mt][nt][half_ * 2 + 0] + bx;
                    float vy = acc[mt][nt][half_ * 2 + 1] + by;
                    if (bnblk < HCOL) {
                        float2 o = {vx, vy};
                        *(float2*)(gYdst + (size_t)r * HCOL + bnblk + cg) = o;
                    } else if (bnblk < 576) {
                        __half2 h = __floats2half2_rn(vx, vy);
                        *(__half2*)(gYB + (size_t)r * 256 + (bnblk - 320) + cg) = h;
                    } else {
                        float2 o = {vx, vy};
                        *(float2*)(gYXn + (size_t)r * 64 + cg) = o;
                    }
                }
            }
        }
    }
}

// ---------------------------------------------------------------------------
// CSR build
// ---------------------------------------------------------------------------
__global__ void count_kernel(const int* __restrict__ dst, int E) {
    int i = blockIdx.x * blockDim.x + threadIdx.x;
    if (i < E) atomicAdd(&gCount[dst[i]], 1);
}

__global__ void scan_kernel(int N) {
    __shared__ int sm[1024];
    int tid = threadIdx.x;
    int chunk = (N + 1023) / 1024;
    int start = tid * chunk;
    int end = start + chunk;
    if (end > N) end = N;
    if (start > N) start = N;
    int s = 0;
    for (int i = start; i < end; i++) s += gCount[i];
    sm[tid] = s;
    __syncthreads();
    for (int off = 1; off < 1024; off <<= 1) {
        int v = (tid >= off) ? sm[tid - off] : 0;
        __syncthreads();
        sm[tid] += v;
        __syncthreads();
    }
    int run = (tid == 0) ? 0 : sm[tid - 1];
    for (int i = start; i < end; i++) {
        gOff[i] = run;
        gCur[i] = run;
        run += gCount[i];
    }
    if (tid == 1023) gOff[N] = sm[1023];
}

__global__ void scatter_kernel(const int* __restrict__ src, const int* __restrict__ dst, int E) {
    int i = blockIdx.x * blockDim.x + threadIdx.x;
    if (i < E) {
        int p = atomicAdd(&gCur[dst[i]], 1);
        gCsr[p] = src[i];
    }
}

// ---------------------------------------------------------------------------
// Aggregation: one warp per dst node, thread owns 2 channels.
// gYdst row: [A0..A3 | Xv] fp32; gYB row: [B0..B3] fp16; gYXn row: [Xn] fp32
// ---------------------------------------------------------------------------
__global__ __launch_bounds__(256) void aggregate_kernel(float* __restrict__ out, int N) {
    int w = (blockIdx.x * blockDim.x + threadIdx.x) >> 5;
    int lane = threadIdx.x & 31;
    if (w >= N) return;
    const float* rowD = gYdst + (size_t)w * HCOL;
    int c = lane * 2;

    float2 a0 = *(const float2*)(rowD + 0 + c);
    float2 a1 = *(const float2*)(rowD + 64 + c);
    float2 a2 = *(const float2*)(rowD + 128 + c);
    float2 a3 = *(const float2*)(rowD + 192 + c);
    float2 xv = *(const float2*)(rowD + 256 + c);

    const __half2* rbSelf = (const __half2*)(gYB + (size_t)w * 256);
    float2 s0 = __half22float2(rbSelf[lane]);
    float2 s1 = __half22float2(rbSelf[32 + lane]);
    float2 s2 = __half22float2(rbSelf[64 + lane]);
    float2 s3 = __half22float2(rbSelf[96 + lane]);

    const float Kc = 0.25f * 1.4426950408889634f;  // log2(e)/4

    float sx = fmaxf(a0.x + s0.x, 0.f) + fmaxf(a1.x + s1.x, 0.f) +
               fmaxf(a2.x + s2.x, 0.f) + fmaxf(a3.x + s3.x, 0.f);
    float sy = fmaxf(a0.y + s0.y, 0.f) + fmaxf(a1.y + s1.y, 0.f) +
               fmaxf(a2.y + s2.y, 0.f) + fmaxf(a3.y + s3.y, 0.f);
    float ex, ey;
    asm("ex2.approx.f32 %0, %1;" : "=f"(ex) : "f"(sx * Kc));
    asm("ex2.approx.f32 %0, %1;" : "=f"(ey) : "f"(sy * Kc));
    float denx = ex, deny = ey;
    float numx = ex * xv.x, numy = ey * xv.y;

    int j = gOff[w];
    int end = gOff[w + 1];
    #pragma unroll 2
    for (; j < end; j++) {
        int s = gCsr[j];
        const __half2* rb = (const __half2*)(gYB + (size_t)s * 256);
        float2 b0 = __half22float2(rb[lane]);
        float2 b1 = __half22float2(rb[32 + lane]);
        float2 b2 = __half22float2(rb[64 + lane]);
        float2 b3 = __half22float2(rb[96 + lane]);
        float2 xn = *(const float2*)(gYXn + (size_t)s * 64 + c);
        float tx = fmaxf(a0.x + b0.x, 0.f) + fmaxf(a1.x + b1.x, 0.f) +
                   fmaxf(a2.x + b2.x, 0.f) + fmaxf(a3.x + b3.x, 0.f);
        float ty = fmaxf(a0.y + b0.y, 0.f) + fmaxf(a1.y + b1.y, 0.f) +
                   fmaxf(a2.y + b2.y, 0.f) + fmaxf(a3.y + b3.y, 0.f);
        float g1, g2;
        asm("ex2.approx.f32 %0, %1;" : "=f"(g1) : "f"(tx * Kc));
        asm("ex2.approx.f32 %0, %1;" : "=f"(g2) : "f"(ty * Kc));
        denx += g1;
        deny += g2;
        numx = fmaf(g1, xn.x, numx);
        numy = fmaf(g2, xn.y, numy);
    }

    float2 o;
    o.x = fmaxf(numx / denx, 0.f);
    o.y = fmaxf(numy / deny, 0.f);
    *(float2*)(out + (size_t)w * 64 + c) = o;
}

// ---------------------------------------------------------------------------
// Launch — CSR build forked onto a side stream, overlapped with prep+GEMM.
// ---------------------------------------------------------------------------
static cudaStream_t g_s2 = nullptr;
static cudaEvent_t g_evFork = nullptr, g_evJoin = nullptr;

extern "C" void kernel_launch(void* const* d_in, const int* in_sizes, int n_in,
                              void* d_out, int out_size) {
    const float* x   = (const float*)d_in[0];
    const int*   src = (const int*)d_in[1];
    const int*   dst = (const int*)d_in[2];
    const float* Wv  = (const float*)d_in[3];
    const float* bv  = (const float*)d_in[4];
    const float* Wn  = (const float*)d_in[5];
    const float* bn  = (const float*)d_in[6];
    const float* Wt  = (const float*)d_in[7];
    const float* bt  = (const float*)d_in[8];
    const float* Wa  = (const float*)d_in[9];
    const float* ba  = (const float*)d_in[10];
    float* out = (float*)d_out;

    int N = in_sizes[0] / 128;
    int E = in_sizes[1];

    if (g_s2 == nullptr) {
        cudaFuncSetAttribute(gemm_tc_kernel,
                             cudaFuncAttributeMaxDynamicSharedMemorySize, GEMM_SMEM);
        cudaStreamCreateWithFlags(&g_s2, cudaStreamNonBlocking);
        cudaEventCreateWithFlags(&g_evFork, cudaEventDisableTiming);
        cudaEventCreateWithFlags(&g_evJoin, cudaEventDisableTiming);
    }

    // Fork side stream off the (possibly capturing) default stream
    cudaEventRecord(g_evFork, 0);
    cudaStreamWaitEvent(g_s2, g_evFork, 0);

    // Side stream: CSR build (depends only on src/dst)
    zero_kernel<<<(N + 255) / 256, 256, 0, g_s2>>>(N);
    count_kernel<<<(E + 255) / 256, 256, 0, g_s2>>>(dst, E);
    scan_kernel<<<1, 1024, 0, g_s2>>>(N);
    scatter_kernel<<<(E + 255) / 256, 256, 0, g_s2>>>(src, dst, E);
    cudaEventRecord(g_evJoin, g_s2);

    // Main stream: weight fold + node GEMM
    prep_kernel<<<(128 * NCOL + 255) / 256, 256>>>(Wv, bv, Wn, bn, Wt, bt, Wa, ba);
    dim3 gg((N + 127) / 128, NCOL / 64);
    gemm_tc_kernel<<<gg, 256, GEMM_SMEM>>>(x, N);

    // Join and aggregate
    cudaStreamWaitEvent(0, g_evJoin, 0);
    aggregate_kernel<<<(N * 32 + 255) / 256, 256>>>(out, N);
}

// round 4
// speedup vs baseline: 1.4605x; 1.4605x over previous
#include <cuda_runtime.h>
#include <cuda_fp16.h>
#include <cstdint>
#include <cstddef>

#define N_CAP 50000
#define E_CAP 1600000
#define NCOL  640
#define HCOL  320

// Scratch (static __device__ — no allocation in kernel_launch)
__device__ float  gU[128 * NCOL];
__device__ float  gC[NCOL];
__device__ float  gYdst[(size_t)N_CAP * HCOL];   // [A0..A3 | Xv]  fp32
__device__ __half gYB[(size_t)N_CAP * 256];      // [B0..B3]       fp16
__device__ float  gYXn[(size_t)N_CAP * 64];      // [Xn]           fp32
__device__ int    gCount[N_CAP];
__device__ int    gOff[N_CAP + 1];
__device__ int    gCur[N_CAP];
__device__ int    gCsr[E_CAP];

// ---------------------------------------------------------------------------
__global__ void zero_kernel(int N) {
    int i = blockIdx.x * blockDim.x + threadIdx.x;
    if (i < N) gCount[i] = 0;
}

// ---------------------------------------------------------------------------
// Fold weights into U'[128 x 640], c[640]
// col layout: [A heads: 0-255 | Xv: 256-319 | B heads: 320-575 | Xn: 576-639]
//   A_i = Wt_i @ Wa_i[0:64,:]    bias: ba_i + bt_i@(Wa_top + Wa_bot)
//   B_i = Wt_i @ Wa_i[64:128,:]  bias 0
// ---------------------------------------------------------------------------
__global__ void prep_kernel(const float* __restrict__ Wv, const float* __restrict__ bv,
                            const float* __restrict__ Wn, const float* __restrict__ bn,
                            const float* __restrict__ Wt, const float* __restrict__ bt,
                            const float* __restrict__ Wa, const float* __restrict__ ba) {
    int tid = blockIdx.x * blockDim.x + threadIdx.x;
    if (tid < 128 * NCOL) {
        int k = tid / NCOL;
        int col = tid % NCOL;
        float v;
        if (col < 256 || (col >= 320 && col < 576)) {
            int top = (col < 256) ? 1 : 0;
            int cc = top ? col : (col - 320);
            int i = (cc >> 6) & 3;
            int j = cc & 63;
            const float* wt = Wt + ((size_t)i * 128 + k) * 64;        // Wt[i][k][*]
            const float* wa = Wa + (size_t)i * 128 * 64 + (top ? 0 : 64 * 64) + j;
            float s = 0.f;
            #pragma unroll 8
            for (int m = 0; m < 64; m++) s += wt[m] * wa[m * 64];
            v = s;
        } else if (col < 320) {
            v = Wv[k * 64 + (col - 256)];
        } else {
            v = Wn[k * 64 + (col - 576)];
        }
        gU[tid] = v;
    }
    if (tid < NCOL) {
        float c;
        if (tid < 256) {
            int i = tid >> 6, j = tid & 63;
            const float* btp = bt + i * 64;
            const float* wa = Wa + (size_t)i * 128 * 64 + j;
            float s = ba[i * 64 + j];
            #pragma unroll 8
            for (int m = 0; m < 64; m++)
                s += btp[m] * (wa[m * 64] + wa[(64 + m) * 64]);
            c = s;
        } else if (tid < 320) {
            c = bv[tid - 256];
        } else if (tid < 576) {
            c = 0.f;
        } else {
            c = bn[tid - 576];
        }
        gC[tid] = c;
    }
}

// ---------------------------------------------------------------------------
// TF32 tensor-core GEMM: Y[M x 640] = X[M x 128] @ U'[128 x 640] + c
// BM=128, BN=64, full K=128 resident in smem. 8 warps, 32x32 per warp.
// Epilogue routes: cols<320 -> gYdst (fp32); 320..575 -> gYB (fp16);
//                  576..639 -> gYXn (fp32).
// ---------------------------------------------------------------------------
#define A_LD 132
#define B_LD 72
#define GEMM_SMEM ((128 * A_LD + 128 * B_LD) * 4)

__device__ __forceinline__ uint32_t f2tf32(float f) {
    uint32_t r;
    asm("cvt.rna.tf32.f32 %0, %1;" : "=r"(r) : "f"(f));
    return r;
}

__global__ __launch_bounds__(256) void gemm_tc_kernel(const float* __restrict__ X, int M) {
    extern __shared__ float smem[];
    float* As = smem;                 // [128][132]
    float* Bs = smem + 128 * A_LD;    // [128][72]

    int tid = threadIdx.x;
    int bm = blockIdx.x * 128;
    int bnblk = blockIdx.y * 64;

    #pragma unroll
    for (int it = 0; it < 16; it++) {
        int idx = tid + it * 256;
        int r = idx >> 5;
        int c4 = (idx & 31) << 2;
        float4 v = make_float4(0.f, 0.f, 0.f, 0.f);
        if (bm + r < M) v = *(const float4*)(X + (size_t)(bm + r) * 128 + c4);
        float4 o;
        o.x = __uint_as_float(f2tf32(v.x));
        o.y = __uint_as_float(f2tf32(v.y));
        o.z = __uint_as_float(f2tf32(v.z));
        o.w = __uint_as_float(f2tf32(v.w));
        *(float4*)(As + r * A_LD + c4) = o;
    }
    #pragma unroll
    for (int it = 0; it < 8; it++) {
        int idx = tid + it * 256;
        int k = idx >> 4;
        int c4 = (idx & 15) << 2;
        float4 v = *(const float4*)(gU + (size_t)k * NCOL + bnblk + c4);
        float4 o;
        o.x = __uint_as_float(f2tf32(v.x));
        o.y = __uint_as_float(f2tf32(v.y));
        o.z = __uint_as_float(f2tf32(v.z));
        o.w = __uint_as_float(f2tf32(v.w));
        *(float4*)(Bs + k * B_LD + c4) = o;
    }
    __syncthreads();

    int w = tid >> 5, lane = tid & 31;
    int g = lane >> 2, tig = lane & 3;
    int wm = (w >> 1) * 32;
    int wn = (w & 1) * 32;

    float acc[2][4][4];
    #pragma unroll
    for (int mt = 0; mt < 2; mt++)
        #pragma unroll
        for (int nt = 0; nt < 4; nt++)
            #pragma unroll
            for (int q = 0; q < 4; q++) acc[mt][nt][q] = 0.f;

    #pragma unroll
    for (int kc = 0; kc < 16; kc++) {
        int kb = kc * 8;
        uint32_t a[2][4], b[4][2];
        #pragma unroll
        for (int mt = 0; mt < 2; mt++) {
            int r0 = wm + mt * 16 + g;
            a[mt][0] = __float_as_uint(As[r0 * A_LD + kb + tig]);
            a[mt][1] = __float_as_uint(As[(r0 + 8) * A_LD + kb + tig]);
            a[mt][2] = __float_as_uint(As[r0 * A_LD + kb + tig + 4]);
            a[mt][3] = __float_as_uint(As[(r0 + 8) * A_LD + kb + tig + 4]);
        }
        #pragma unroll
        for (int nt = 0; nt < 4; nt++) {
            int n0 = wn + nt * 8 + g;
            b[nt][0] = __float_as_uint(Bs[(kb + tig) * B_LD + n0]);
            b[nt][1] = __float_as_uint(Bs[(kb + tig + 4) * B_LD + n0]);
        }
        #pragma unroll
        for (int mt = 0; mt < 2; mt++)
            #pragma unroll
            for (int nt = 0; nt < 4; nt++) {
                asm volatile(
                    "mma.sync.aligned.m16n8k8.row.col.f32.tf32.tf32.f32 "
                    "{%0,%1,%2,%3}, {%4,%5,%6,%7}, {%8,%9}, {%0,%1,%2,%3};\n"
                    : "+f"(acc[mt][nt][0]), "+f"(acc[mt][nt][1]),
                      "+f"(acc[mt][nt][2]), "+f"(acc[mt][nt][3])
                    : "r"(a[mt][0]), "r"(a[mt][1]), "r"(a[mt][2]), "r"(a[mt][3]),
                      "r"(b[nt][0]), "r"(b[nt][1]));
            }
    }

    // --- Epilogue: add bias, route by column block ---
    #pragma unroll
    for (int nt = 0; nt < 4; nt++) {
        int cg = wn + nt * 8 + tig * 2;
        float bx = gC[bnblk + cg];
        float by = gC[bnblk + cg + 1];
        #pragma unroll
        for (int mt = 0; mt < 2; mt++) {
            #pragma unroll
            for (int half_ : {0, 1}) {
                int r = bm + wm + mt * 16 + g + half_ * 8;
                if (r < M) {
                    float vx = acc[mt][nt][half_ * 2 + 0] + bx;
                    float vy = acc[mt][nt][half_ * 2 + 1] + by;
                    if (bnblk < HCOL) {
                        float2 o = {vx, vy};
                        *(float2*)(gYdst + (size_t)r * HCOL + bnblk + cg) = o;
                    } else if (bnblk < 576) {
                        __half2 h = __floats2half2_rn(vx, vy);
                        *(__half2*)(gYB + (size_t)r * 256 + (bnblk - 320) + cg) = h;
                    } else {
                        float2 o = {vx, vy};
                        *(float2*)(gYXn + (size_t)r * 64 + cg) = o;
                    }
                }
            }
        }
    }
}

// ---------------------------------------------------------------------------
// CSR build
// ---------------------------------------------------------------------------
__global__ void count_kernel(const int* __restrict__ dst, int E) {
    int i = blockIdx.x * blockDim.x + threadIdx.x;
    if (i < E) atomicAdd(&gCount[dst[i]], 1);
}

__global__ void scan_kernel(int N) {
    __shared__ int sm[1024];
    int tid = threadIdx.x;
    int chunk = (N + 1023) / 1024;
    int start = tid * chunk;
    int end = start + chunk;
    if (end > N) end = N;
    if (start > N) start = N;
    int s = 0;
    for (int i = start; i < end; i++) s += gCount[i];
    sm[tid] = s;
    __syncthreads();
    for (int off = 1; off < 1024; off <<= 1) {
        int v = (tid >= off) ? sm[tid - off] : 0;
        __syncthreads();
        sm[tid] += v;
        __syncthreads();
    }
    int run = (tid == 0) ? 0 : sm[tid - 1];
    for (int i = start; i < end; i++) {
        gOff[i] = run;
        gCur[i] = run;
        run += gCount[i];
    }
    if (tid == 1023) gOff[N] = sm[1023];
}

__global__ void scatter_kernel(const int* __restrict__ src, const int* __restrict__ dst, int E) {
    int i = blockIdx.x * blockDim.x + threadIdx.x;
    if (i < E) {
        int p = atomicAdd(&gCur[dst[i]], 1);
        gCsr[p] = src[i];
    }
}

// ---------------------------------------------------------------------------
// Aggregation: one warp per dst node, thread owns 2 channels.
// gYdst row: [A0..A3 | Xv] fp32; gYB row: [B0..B3] fp16; gYXn row: [Xn] fp32
// ---------------------------------------------------------------------------
__global__ __launch_bounds__(256) void aggregate_kernel(float* __restrict__ out, int N) {
    int w = (blockIdx.x * blockDim.x + threadIdx.x) >> 5;
    int lane = threadIdx.x & 31;
    if (w >= N) return;
    const float* rowD = gYdst + (size_t)w * HCOL;
    int c = lane * 2;

    float2 a0 = *(const float2*)(rowD + 0 + c);
    float2 a1 = *(const float2*)(rowD + 64 + c);
    float2 a2 = *(const float2*)(rowD + 128 + c);
    float2 a3 = *(const float2*)(rowD + 192 + c);
    float2 xv = *(const float2*)(rowD + 256 + c);

    const __half2* rbSelf = (const __half2*)(gYB + (size_t)w * 256);
    float2 s0 = __half22float2(rbSelf[lane]);
    float2 s1 = __half22float2(rbSelf[32 + lane]);
    float2 s2 = __half22float2(rbSelf[64 + lane]);
    float2 s3 = __half22float2(rbSelf[96 + lane]);

    const float Kc = 0.25f * 1.4426950408889634f;  // log2(e)/4

    float sx = fmaxf(a0.x + s0.x, 0.f) + fmaxf(a1.x + s1.x, 0.f) +
               fmaxf(a2.x + s2.x, 0.f) + fmaxf(a3.x + s3.x, 0.f);
    float sy = fmaxf(a0.y + s0.y, 0.f) + fmaxf(a1.y + s1.y, 0.f) +
               fmaxf(a2.y + s2.y, 0.f) + fmaxf(a3.y + s3.y, 0.f);
    float ex, ey;
    asm("ex2.approx.f32 %0, %1;" : "=f"(ex) : "f"(sx * Kc));
    asm("ex2.approx.f32 %0, %1;" : "=f"(ey) : "f"(sy * Kc));
    float denx = ex, deny = ey;
    float numx = ex * xv.x, numy = ey * xv.y;

    int j = gOff[w];
    int end = gOff[w + 1];
    #pragma unroll 2
    for (; j < end; j++) {
        int s = gCsr[j];
        const __half2* rb = (const __half2*)(gYB + (size_t)s * 256);
        float2 b0 = __half22float2(rb[lane]);
        float2 b1 = __half22float2(rb[32 + lane]);
        float2 b2 = __half22float2(rb[64 + lane]);
        float2 b3 = __half22float2(rb[96 + lane]);
        float2 xn = *(const float2*)(gYXn + (size_t)s * 64 + c);
        float tx = fmaxf(a0.x + b0.x, 0.f) + fmaxf(a1.x + b1.x, 0.f) +
                   fmaxf(a2.x + b2.x, 0.f) + fmaxf(a3.x + b3.x, 0.f);
        float ty = fmaxf(a0.y + b0.y, 0.f) + fmaxf(a1.y + b1.y, 0.f) +
                   fmaxf(a2.y + b2.y, 0.f) + fmaxf(a3.y + b3.y, 0.f);
        float g1, g2;
        asm("ex2.approx.f32 %0, %1;" : "=f"(g1) : "f"(tx * Kc));
        asm("ex2.approx.f32 %0, %1;" : "=f"(g2) : "f"(ty * Kc));
        denx += g1;
        deny += g2;
        numx = fmaf(g1, xn.x, numx);
        numy = fmaf(g2, xn.y, numy);
    }

    float2 o;
    o.x = fmaxf(numx / denx, 0.f);
    o.y = fmaxf(numy / deny, 0.f);
    *(float2*)(out + (size_t)w * 64 + c) = o;
}

// ---------------------------------------------------------------------------
// Launch — CSR build forked onto a side stream, overlapped with prep+GEMM.
// ---------------------------------------------------------------------------
static cudaStream_t g_s2 = nullptr;
static cudaEvent_t g_evFork = nullptr, g_evJoin = nullptr;

extern "C" void kernel_launch(void* const* d_in, const int* in_sizes, int n_in,
                              void* d_out, int out_size) {
    const float* x   = (const float*)d_in[0];
    const int*   src = (const int*)d_in[1];
    const int*   dst = (const int*)d_in[2];
    const float* Wv  = (const float*)d_in[3];
    const float* bv  = (const float*)d_in[4];
    const float* Wn  = (const float*)d_in[5];
    const float* bn  = (const float*)d_in[6];
    const float* Wt  = (const float*)d_in[7];
    const float* bt  = (const float*)d_in[8];
    const float* Wa  = (const float*)d_in[9];
    const float* ba  = (const float*)d_in[10];
    float* out = (float*)d_out;

    int N = in_sizes[0] / 128;
    int E = in_sizes[1];

    if (g_s2 == nullptr) {
        cudaFuncSetAttribute(gemm_tc_kernel,
                             cudaFuncAttributeMaxDynamicSharedMemorySize, GEMM_SMEM);
        cudaStreamCreateWithFlags(&g_s2, cudaStreamNonBlocking);
        cudaEventCreateWithFlags(&g_evFork, cudaEventDisableTiming);
        cudaEventCreateWithFlags(&g_evJoin, cudaEventDisableTiming);
    }

    // Fork side stream off the (possibly capturing) default stream
    cudaEventRecord(g_evFork, 0);
    cudaStreamWaitEvent(g_s2, g_evFork, 0);

    // Side stream: CSR build (depends only on src/dst)
    zero_kernel<<<(N + 255) / 256, 256, 0, g_s2>>>(N);
    count_kernel<<<(E + 255) / 256, 256, 0, g_s2>>>(dst, E);
    scan_kernel<<<1, 1024, 0, g_s2>>>(N);
    scatter_kernel<<<(E + 255) / 256, 256, 0, g_s2>>>(src, dst, E);
    cudaEventRecord(g_evJoin, g_s2);

    // Main stream: weight fold + node GEMM
    prep_kernel<<<(128 * NCOL + 255) / 256, 256>>>(Wv, bv, Wn, bn, Wt, bt, Wa, ba);
    dim3 gg((N + 127) / 128, NCOL / 64);
    gemm_tc_kernel<<<gg, 256, GEMM_SMEM>>>(x, N);

    // Join and aggregate
    cudaStreamWaitEvent(0, g_evJoin, 0);
    aggregate_kernel<<<(N * 32 + 255) / 256, 256>>>(out, N);
}

// round 5
// speedup vs baseline: 1.4920x; 1.0215x over previous
#include <cuda_runtime.h>
#include <cuda_fp16.h>
#include <cstdint>
#include <cstddef>

#define N_CAP 50000
#define E_CAP 1600000
#define NCOL  640
#define HCOL  320

// Scratch (static __device__ — no allocation in kernel_launch)
__device__ float   gU[128 * NCOL];
__device__ float   gC[NCOL];
__device__ float   gYdst[(size_t)N_CAP * HCOL];   // [A0..A3 | Xv]  fp32
// Per-edge-gather data, lane-interleaved:
//   gEB : per node 128 half2 (512 B). lane l, head h at index l*4 + h
//         (so one float4 per lane = all 4 heads' channel pair (2l, 2l+1))
//   gEXn: per node 32 half2 (128 B). lane l at index l (channels 2l, 2l+1)
__device__ __half2 gEB[(size_t)N_CAP * 128];
__device__ __half2 gEXn[(size_t)N_CAP * 32];
__device__ int     gCount[N_CAP];
__device__ int     gOff[N_CAP + 1];
__device__ int     gCur[N_CAP];
__device__ int     gCsr[E_CAP];

// ---------------------------------------------------------------------------
__global__ void zero_kernel(int N) {
    int i = blockIdx.x * blockDim.x + threadIdx.x;
    if (i < N) gCount[i] = 0;
}

// ---------------------------------------------------------------------------
// Fold weights into U'[128 x 640], c[640]
// col layout: [A heads: 0-255 | Xv: 256-319 | B heads: 320-575 | Xn: 576-639]
//   A_i = Wt_i @ Wa_i[0:64,:]    bias: ba_i + bt_i@(Wa_top + Wa_bot)
//   B_i = Wt_i @ Wa_i[64:128,:]  bias 0
// ---------------------------------------------------------------------------
__global__ void prep_kernel(const float* __restrict__ Wv, const float* __restrict__ bv,
                            const float* __restrict__ Wn, const float* __restrict__ bn,
                            const float* __restrict__ Wt, const float* __restrict__ bt,
                            const float* __restrict__ Wa, const float* __restrict__ ba) {
    int tid = blockIdx.x * blockDim.x + threadIdx.x;
    if (tid < 128 * NCOL) {
        int k = tid / NCOL;
        int col = tid % NCOL;
        float v;
        if (col < 256 || (col >= 320 && col < 576)) {
            int top = (col < 256) ? 1 : 0;
            int cc = top ? col : (col - 320);
            int i = (cc >> 6) & 3;
            int j = cc & 63;
            const float* wt = Wt + ((size_t)i * 128 + k) * 64;        // Wt[i][k][*]
            const float* wa = Wa + (size_t)i * 128 * 64 + (top ? 0 : 64 * 64) + j;
            float s = 0.f;
            #pragma unroll 8
            for (int m = 0; m < 64; m++) s += wt[m] * wa[m * 64];
            v = s;
        } else if (col < 320) {
            v = Wv[k * 64 + (col - 256)];
        } else {
            v = Wn[k * 64 + (col - 576)];
        }
        gU[tid] = v;
    }
    if (tid < NCOL) {
        float c;
        if (tid < 256) {
            int i = tid >> 6, j = tid & 63;
            const float* btp = bt + i * 64;
            const float* wa = Wa + (size_t)i * 128 * 64 + j;
            float s = ba[i * 64 + j];
            #pragma unroll 8
            for (int m = 0; m < 64; m++)
                s += btp[m] * (wa[m * 64] + wa[(64 + m) * 64]);
            c = s;
        } else if (tid < 320) {
            c = bv[tid - 256];
        } else if (tid < 576) {
            c = 0.f;
        } else {
            c = bn[tid - 576];
        }
        gC[tid] = c;
    }
}

// ---------------------------------------------------------------------------
// TF32 tensor-core GEMM: Y[M x 640] = X[M x 128] @ U'[128 x 640] + c
// BM=128, BN=64, full K=128 resident in smem. 8 warps, 32x32 per warp.
// Epilogue routes: cols<320 -> gYdst fp32; 320..575 -> gEB fp16 (interleaved);
//                  576..639 -> gEXn fp16.
// ---------------------------------------------------------------------------
#define A_LD 132
#define B_LD 72
#define GEMM_SMEM ((128 * A_LD + 128 * B_LD) * 4)

__device__ __forceinline__ uint32_t f2tf32(float f) {
    uint32_t r;
    asm("cvt.rna.tf32.f32 %0, %1;" : "=r"(r) : "f"(f));
    return r;
}

__global__ __launch_bounds__(256) void gemm_tc_kernel(const float* __restrict__ X, int M) {
    extern __shared__ float smem[];
    float* As = smem;                 // [128][132]
    float* Bs = smem + 128 * A_LD;    // [128][72]

    int tid = threadIdx.x;
    int bm = blockIdx.x * 128;
    int bnblk = blockIdx.y * 64;

    #pragma unroll
    for (int it = 0; it < 16; it++) {
        int idx = tid + it * 256;
        int r = idx >> 5;
        int c4 = (idx & 31) << 2;
        float4 v = make_float4(0.f, 0.f, 0.f, 0.f);
        if (bm + r < M) v = *(const float4*)(X + (size_t)(bm + r) * 128 + c4);
        float4 o;
        o.x = __uint_as_float(f2tf32(v.x));
        o.y = __uint_as_float(f2tf32(v.y));
        o.z = __uint_as_float(f2tf32(v.z));
        o.w = __uint_as_float(f2tf32(v.w));
        *(float4*)(As + r * A_LD + c4) = o;
    }
    #pragma unroll
    for (int it = 0; it < 8; it++) {
        int idx = tid + it * 256;
        int k = idx >> 4;
        int c4 = (idx & 15) << 2;
        float4 v = *(const float4*)(gU + (size_t)k * NCOL + bnblk + c4);
        float4 o;
        o.x = __uint_as_float(f2tf32(v.x));
        o.y = __uint_as_float(f2tf32(v.y));
        o.z = __uint_as_float(f2tf32(v.z));
        o.w = __uint_as_float(f2tf32(v.w));
        *(float4*)(Bs + k * B_LD + c4) = o;
    }
    __syncthreads();

    int w = tid >> 5, lane = tid & 31;
    int g = lane >> 2, tig = lane & 3;
    int wm = (w >> 1) * 32;
    int wn = (w & 1) * 32;

    float acc[2][4][4];
    #pragma unroll
    for (int mt = 0; mt < 2; mt++)
        #pragma unroll
        for (int nt = 0; nt < 4; nt++)
            #pragma unroll
            for (int q = 0; q < 4; q++) acc[mt][nt][q] = 0.f;

    #pragma unroll
    for (int kc = 0; kc < 16; kc++) {
        int kb = kc * 8;
        uint32_t a[2][4], b[4][2];
        #pragma unroll
        for (int mt = 0; mt < 2; mt++) {
            int r0 = wm + mt * 16 + g;
            a[mt][0] = __float_as_uint(As[r0 * A_LD + kb + tig]);
            a[mt][1] = __float_as_uint(As[(r0 + 8) * A_LD + kb + tig]);
            a[mt][2] = __float_as_uint(As[r0 * A_LD + kb + tig + 4]);
            a[mt][3] = __float_as_uint(As[(r0 + 8) * A_LD + kb + tig + 4]);
        }
        #pragma unroll
        for (int nt = 0; nt < 4; nt++) {
            int n0 = wn + nt * 8 + g;
            b[nt][0] = __float_as_uint(Bs[(kb + tig) * B_LD + n0]);
            b[nt][1] = __float_as_uint(Bs[(kb + tig + 4) * B_LD + n0]);
        }
        #pragma unroll
        for (int mt = 0; mt < 2; mt++)
            #pragma unroll
            for (int nt = 0; nt < 4; nt++) {
                asm volatile(
                    "mma.sync.aligned.m16n8k8.row.col.f32.tf32.tf32.f32 "
                    "{%0,%1,%2,%3}, {%4,%5,%6,%7}, {%8,%9}, {%0,%1,%2,%3};\n"
                    : "+f"(acc[mt][nt][0]), "+f"(acc[mt][nt][1]),
                      "+f"(acc[mt][nt][2]), "+f"(acc[mt][nt][3])
                    : "r"(a[mt][0]), "r"(a[mt][1]), "r"(a[mt][2]), "r"(a[mt][3]),
                      "r"(b[nt][0]), "r"(b[nt][1]));
            }
    }

    // --- Epilogue: add bias, route by column block ---
    #pragma unroll
    for (int nt = 0; nt < 4; nt++) {
        int cg = wn + nt * 8 + tig * 2;            // even channel in 64-block
        float bx = gC[bnblk + cg];
        float by = gC[bnblk + cg + 1];
        #pragma unroll
        for (int mt = 0; mt < 2; mt++) {
            #pragma unroll
            for (int half_ : {0, 1}) {
                int r = bm + wm + mt * 16 + g + half_ * 8;
                if (r < M) {
                    float vx = acc[mt][nt][half_ * 2 + 0] + bx;
                    float vy = acc[mt][nt][half_ * 2 + 1] + by;
                    if (bnblk < HCOL) {
                        float2 o = {vx, vy};
                        *(float2*)(gYdst + (size_t)r * HCOL + bnblk + cg) = o;
                    } else if (bnblk < 576) {
                        int h = (bnblk - 320) >> 6;        // head 0..3
                        gEB[(size_t)r * 128 + (cg >> 1) * 4 + h] =
                            __floats2half2_rn(vx, vy);
                    } else {
                        gEXn[(size_t)r * 32 + (cg >> 1)] =
                            __floats2half2_rn(vx, vy);
                    }
                }
            }
        }
    }
}

// ---------------------------------------------------------------------------
// CSR build
// ---------------------------------------------------------------------------
__global__ void count_kernel(const int* __restrict__ dst, int E) {
    int i = blockIdx.x * blockDim.x + threadIdx.x;
    if (i < E) atomicAdd(&gCount[dst[i]], 1);
}

__global__ void scan_kernel(int N) {
    __shared__ int sm[1024];
    int tid = threadIdx.x;
    int chunk = (N + 1023) / 1024;
    int start = tid * chunk;
    int end = start + chunk;
    if (end > N) end = N;
    if (start > N) start = N;
    int s = 0;
    for (int i = start; i < end; i++) s += gCount[i];
    sm[tid] = s;
    __syncthreads();
    for (int off = 1; off < 1024; off <<= 1) {
        int v = (tid >= off) ? sm[tid - off] : 0;
        __syncthreads();
        sm[tid] += v;
        __syncthreads();
    }
    int run = (tid == 0) ? 0 : sm[tid - 1];
    for (int i = start; i < end; i++) {
        gOff[i] = run;
        gCur[i] = run;
        run += gCount[i];
    }
    if (tid == 1023) gOff[N] = sm[1023];
}

__global__ void scatter_kernel(const int* __restrict__ src, const int* __restrict__ dst, int E) {
    int i = blockIdx.x * blockDim.x + threadIdx.x;
    if (i < E) {
        int p = atomicAdd(&gCur[dst[i]], 1);
        gCsr[p] = src[i];
    }
}

// ---------------------------------------------------------------------------
// Aggregation: one warp per dst node, thread owns 2 channels (2l, 2l+1).
// Per-edge reads: 1x LDG.128 (gEB float4) + 1x LDG.32 (gEXn half2) per thread.
// ---------------------------------------------------------------------------
union PackB { float4 f; __half2 h[4]; };

__global__ __launch_bounds__(256) void aggregate_kernel(float* __restrict__ out, int N) {
    int w = (blockIdx.x * blockDim.x + threadIdx.x) >> 5;
    int lane = threadIdx.x & 31;
    if (w >= N) return;
    const float* rowD = gYdst + (size_t)w * HCOL;
    int c = lane * 2;

    float2 a0 = *(const float2*)(rowD + 0 + c);
    float2 a1 = *(const float2*)(rowD + 64 + c);
    float2 a2 = *(const float2*)(rowD + 128 + c);
    float2 a3 = *(const float2*)(rowD + 192 + c);
    float2 xv = *(const float2*)(rowD + 256 + c);

    // Self B pack
    PackB ps;
    ps.f = ((const float4*)(gEB + (size_t)w * 128))[lane];
    float2 s0 = __half22float2(ps.h[0]);
    float2 s1 = __half22float2(ps.h[1]);
    float2 s2 = __half22float2(ps.h[2]);
    float2 s3 = __half22float2(ps.h[3]);

    const float Kc = 0.25f * 1.4426950408889634f;  // log2(e)/4

    float sx = fmaxf(a0.x + s0.x, 0.f) + fmaxf(a1.x + s1.x, 0.f) +
               fmaxf(a2.x + s2.x, 0.f) + fmaxf(a3.x + s3.x, 0.f);
    float sy = fmaxf(a0.y + s0.y, 0.f) + fmaxf(a1.y + s1.y, 0.f) +
               fmaxf(a2.y + s2.y, 0.f) + fmaxf(a3.y + s3.y, 0.f);
    float ex, ey;
    asm("ex2.approx.f32 %0, %1;" : "=f"(ex) : "f"(sx * Kc));
    asm("ex2.approx.f32 %0, %1;" : "=f"(ey) : "f"(sy * Kc));
    float denx = ex, deny = ey;
    float numx = ex * xv.x, numy = ey * xv.y;

    int j = gOff[w];
    int end = gOff[w + 1];
    #pragma unroll 4
    for (; j < end; j++) {
        int s = gCsr[j];
        PackB pb;
        pb.f = ((const float4*)(gEB + (size_t)s * 128))[lane];
        float2 xn = __half22float2(gEXn[(size_t)s * 32 + lane]);
        float2 b0 = __half22float2(pb.h[0]);
        float2 b1 = __half22float2(pb.h[1]);
        float2 b2 = __half22float2(pb.h[2]);
        float2 b3 = __half22float2(pb.h[3]);
        float tx = fmaxf(a0.x + b0.x, 0.f) + fmaxf(a1.x + b1.x, 0.f) +
                   fmaxf(a2.x + b2.x, 0.f) + fmaxf(a3.x + b3.x, 0.f);
        float ty = fmaxf(a0.y + b0.y, 0.f) + fmaxf(a1.y + b1.y, 0.f) +
                   fmaxf(a2.y + b2.y, 0.f) + fmaxf(a3.y + b3.y, 0.f);
        float g1, g2;
        asm("ex2.approx.f32 %0, %1;" : "=f"(g1) : "f"(tx * Kc));
        asm("ex2.approx.f32 %0, %1;" : "=f"(g2) : "f"(ty * Kc));
        denx += g1;
        deny += g2;
        numx = fmaf(g1, xn.x, numx);
        numy = fmaf(g2, xn.y, numy);
    }

    float2 o;
    o.x = fmaxf(numx / denx, 0.f);
    o.y = fmaxf(numy / deny, 0.f);
    *(float2*)(out + (size_t)w * 64 + c) = o;
}

// ---------------------------------------------------------------------------
// Launch — CSR build forked onto a side stream, overlapped with prep+GEMM.
// ---------------------------------------------------------------------------
static cudaStream_t g_s2 = nullptr;
static cudaEvent_t g_evFork = nullptr, g_evJoin = nullptr;

extern "C" void kernel_launch(void* const* d_in, const int* in_sizes, int n_in,
                              void* d_out, int out_size) {
    const float* x   = (const float*)d_in[0];
    const int*   src = (const int*)d_in[1];
    const int*   dst = (const int*)d_in[2];
    const float* Wv  = (const float*)d_in[3];
    const float* bv  = (const float*)d_in[4];
    const float* Wn  = (const float*)d_in[5];
    const float* bn  = (const float*)d_in[6];
    const float* Wt  = (const float*)d_in[7];
    const float* bt  = (const float*)d_in[8];
    const float* Wa  = (const float*)d_in[9];
    const float* ba  = (const float*)d_in[10];
    float* out = (float*)d_out;

    int N = in_sizes[0] / 128;
    int E = in_sizes[1];

    if (g_s2 == nullptr) {
        cudaFuncSetAttribute(gemm_tc_kernel,
                             cudaFuncAttributeMaxDynamicSharedMemorySize, GEMM_SMEM);
        cudaStreamCreateWithFlags(&g_s2, cudaStreamNonBlocking);
        cudaEventCreateWithFlags(&g_evFork, cudaEventDisableTiming);
        cudaEventCreateWithFlags(&g_evJoin, cudaEventDisableTiming);
    }

    // Fork side stream off the (possibly capturing) default stream
    cudaEventRecord(g_evFork, 0);
    cudaStreamWaitEvent(g_s2, g_evFork, 0);

    // Side stream: CSR build (depends only on src/dst)
    zero_kernel<<<(N + 255) / 256, 256, 0, g_s2>>>(N);
    count_kernel<<<(E + 255) / 256, 256, 0, g_s2>>>(dst, E);
    scan_kernel<<<1, 1024, 0, g_s2>>>(N);
    scatter_kernel<<<(E + 255) / 256, 256, 0, g_s2>>>(src, dst, E);
    cudaEventRecord(g_evJoin, g_s2);

    // Main stream: weight fold + node GEMM
    prep_kernel<<<(128 * NCOL + 255) / 256, 256>>>(Wv, bv, Wn, bn, Wt, bt, Wa, ba);
    dim3 gg((N + 127) / 128, NCOL / 64);
    gemm_tc_kernel<<<gg, 256, GEMM_SMEM>>>(x, N);

    // Join and aggregate
    cudaStreamWaitEvent(0, g_evJoin, 0);
    aggregate_kernel<<<(N * 32 + 255) / 256, 256>>>(out, N);
}